// round 16
// baseline (speedup 1.0000x reference)
#include <cuda_runtime.h>
#include <cuda_bf16.h>
#include <math.h>
#include <cstdint>

#define NB      4096
#define PAD     (NB / 2)
#define BATCH   8192
#define T       512
#define NWARP   (T / 32)          // 16
#define GRID_N  608               // 152 SMs * 4 CTAs/SM

// ---------------------------------------------------------------------------
// SINGLE fused kernel.
//  Prologue (per CTA, ~40 instrs/thread): p = sigmoid(logits) -> smem via
//    __expf (MUFU); C = log(prod(1-p)) -> ONE __logf/thread, block-reduced.
//  Loop: proven 42.4us structure — u (f32x4 streaming, __ldcs) vs p (LDS),
//    byte-packed grid in double-buffered smem, l as f32 from L2-resident
//    logits, block-reduce -> log_probs, byte_perm gather -> STG.128 __stcs.
//  smem 24.4 KB x 4 CTAs = 98 KB -> L1D keeps ~130 KB.
// ---------------------------------------------------------------------------
__global__ __launch_bounds__(T, 4)
void fused_kernel(const float* __restrict__ logits,
                  const float* __restrict__ u,
                  const int*   __restrict__ shift,
                  float*       __restrict__ masks,
                  float*       __restrict__ log_probs) {
    __shared__ __align__(16) float         s_p[NB];           // 16 KB
    __shared__ __align__(16) unsigned char s_g[2][NB + 16];   // 8.03 KB
    __shared__ float s_red[2][NWARP];
    __shared__ float s_C;

    const int tid  = threadIdx.x;
    const int lane = tid & 31;
    const int warp = tid >> 5;

    const float4* __restrict__ l4 = (const float4*)logits;

    // ---- issue first-row u loads immediately (overlap with prologue) --------
    const int b0 = blockIdx.x;
    const float4* __restrict__ u4_0 = (const float4*)(u + (size_t)b0 * NB);
    float4 ua = __ldcs(&u4_0[tid]);
    float4 ub = __ldcs(&u4_0[tid + T]);
    int    sh = __ldg(&shift[b0]);

    // ---- prologue: p -> smem (cheap __expf), C via product trick ------------
    {
        float prod = 1.0f;
        #pragma unroll
        for (int it = 0; it < 2; ++it) {
            const int v = tid + it * T;            // float4 slot
            float4 L = __ldg(&l4[v]);
            float p0 = 1.0f / (1.0f + __expf(-L.x));
            float p1 = 1.0f / (1.0f + __expf(-L.y));
            float p2 = 1.0f / (1.0f + __expf(-L.z));
            float p3 = 1.0f / (1.0f + __expf(-L.w));
            ((float4*)s_p)[v] = make_float4(p0, p1, p2, p3);
            prod *= (1.0f - p0) * (1.0f - p1) * (1.0f - p2) * (1.0f - p3);
        }
        // 1-p in [0.35,0.65] (logits ~ 0.1*N(0,1)); 8-term product ~4e-3.
        float c = __logf(prod);
        #pragma unroll
        for (int o = 16; o; o >>= 1) c += __shfl_xor_sync(0xFFFFFFFFu, c, o);
        if (lane == 0) s_red[0][warp] = c;
        __syncthreads();
        if (tid == 0) {
            float v = 0.0f;
            #pragma unroll
            for (int i = 0; i < NWARP; i++) v += s_red[0][i];
            s_C = v;
        }
        __syncthreads();
    }
    const float cC = s_C;
    const float4* __restrict__ p4 = (const float4*)s_p;

    // ---- main loop (proven structure) ----------------------------------------
    int buf = 0;
    int b   = b0;
    while (b < BATCH) {
        float4 pa = p4[tid];
        float4 pb = p4[tid + T];
        float4 la = __ldg(&l4[tid]);
        float4 lb = __ldg(&l4[tid + T]);

        uint32_t wa = (ua.x < pa.x ? 0x01u      : 0u)
                    | (ua.y < pa.y ? 0x100u     : 0u)
                    | (ua.z < pa.z ? 0x10000u   : 0u)
                    | (ua.w < pa.w ? 0x1000000u : 0u);
        uint32_t wb = (ub.x < pb.x ? 0x01u      : 0u)
                    | (ub.y < pb.y ? 0x100u     : 0u)
                    | (ub.z < pb.z ? 0x10000u   : 0u)
                    | (ub.w < pb.w ? 0x1000000u : 0u);
        float acc = (ua.x < pa.x ? la.x : 0.0f)
                  + (ua.y < pa.y ? la.y : 0.0f)
                  + (ua.z < pa.z ? la.z : 0.0f)
                  + (ua.w < pa.w ? la.w : 0.0f)
                  + (ub.x < pb.x ? lb.x : 0.0f)
                  + (ub.y < pb.y ? lb.y : 0.0f)
                  + (ub.z < pb.z ? lb.z : 0.0f)
                  + (ub.w < pb.w ? lb.w : 0.0f);

        uint32_t* sw = (uint32_t*)&s_g[buf][0];
        sw[tid]     = wa;
        sw[tid + T] = wb;

        // ---- block reduction -> log_probs[b] --------------------------------
        #pragma unroll
        for (int o = 16; o; o >>= 1) acc += __shfl_xor_sync(0xFFFFFFFFu, acc, o);
        if (lane == 0) s_red[buf][warp] = acc;
        __syncthreads();
        if (warp == 0) {
            float v = (lane < NWARP) ? s_red[buf][lane] : 0.0f;
            #pragma unroll
            for (int o = 8; o; o >>= 1) v += __shfl_xor_sync(0xFFFFFFFFu, v, o);
            if (lane == 0) log_probs[b] = v + cC;
        }

        // ---- prefetch next row's u/shift (overlaps gather+store) -------------
        const int curSh = sh;
        const int bn = b + GRID_N;
        if (bn < BATCH) {
            const float4* __restrict__ u4n = (const float4*)(u + (size_t)bn * NB);
            ua = __ldcs(&u4n[tid]);
            ub = __ldcs(&u4n[tid + T]);
            sh = __ldg(&shift[bn]);
        }

        // ---- reflect-shift gather -> 2x STG.128 (streaming) ------------------
        float4* __restrict__ out4 = (float4*)(masks + (size_t)b * NB);
        #pragma unroll
        for (int it = 0; it < 2; ++it) {
            const int idx  = tid + it * T;
            const int base = curSh + 4 * idx - PAD;
            float4 o4;
            if (base >= 0 && base <= NB - 4) {
                const int wi = base >> 2;
                uint32_t w0 = sw[wi], w1 = sw[wi + 1];        // wi+1 within padding
                uint32_t pk = __byte_perm(w0, w1, 0x3210 + (base & 3) * 0x1111);
                o4.x = __int_as_float((pk & 0xFFu)         * 0x3F800000u);
                o4.y = __int_as_float(((pk >> 8)  & 0xFFu) * 0x3F800000u);
                o4.z = __int_as_float(((pk >> 16) & 0xFFu) * 0x3F800000u);
                o4.w = __int_as_float(((pk >> 24) & 0xFFu) * 0x3F800000u);
            } else {
                float r[4];
                #pragma unroll
                for (int k = 0; k < 4; k++) {
                    int s = base + k;
                    s = (s < 0) ? -s : s;
                    s = (s >= NB) ? (2 * (NB - 1) - s) : s;
                    r[k] = (float)s_g[buf][s];
                }
                o4 = make_float4(r[0], r[1], r[2], r[3]);
            }
            __stcs(&out4[idx], o4);
        }

        b = bn;
        buf ^= 1;
    }
}

// ---------------------------------------------------------------------------
extern "C" void kernel_launch(void* const* d_in, const int* in_sizes, int n_in,
                              void* d_out, int out_size) {
    const float* logits = (const float*)d_in[0];   // (NB,)
    const float* u      = (const float*)d_in[1];   // (B, NB)
    const int*   shift  = (const int*)  d_in[2];   // (B,)

    float* masks     = (float*)d_out;                       // (B, 1, NB)
    float* log_probs = (float*)d_out + (size_t)BATCH * NB;  // (B,)

    fused_kernel<<<GRID_N, T>>>(logits, u, shift, masks, log_probs);
}